// round 16
// baseline (speedup 1.0000x reference)
#include <cuda_runtime.h>
#include <cuda_bf16.h>
#include <cstdint>

#define BB 2
#define CC 128
#define NN 4096
#define THRESH2 64.0f
#define BN_EPS 1e-5f

// ---------------- scratch (device globals) -----------------------------------
__device__ __nv_bfloat16 g_xb[BB * NN * CC];
__device__ __nv_bfloat16 g_xl[BB * NN * CC];
__device__ __nv_bfloat16 g_Whi[CC * CC];
__device__ __nv_bfloat16 g_Wlo[CC * CC];
__device__ float g_sqp[4][BB * NN];
__device__ float g_y [BB * NN * CC];
__device__ unsigned int g_Hb[(size_t)BB * NN * (NN / 32)];
__device__ float g_partT[2][CC][512];
__device__ float g_mean[CC];
__device__ float g_rstd[CC];
__device__ unsigned int g_barcnt = 0;
__device__ unsigned int g_bargen = 0;

__device__ __forceinline__ uint32_t smem_u32(const void* p) {
    uint32_t a;
    asm("{ .reg .u64 t; cvta.to.shared.u64 t, %1; cvt.u32.u64 %0, t; }" : "=r"(a) : "l"(p));
    return a;
}
__device__ __forceinline__ void ldm_x4(uint32_t a[4], uint32_t addr) {
    asm volatile("ldmatrix.sync.aligned.m8n8.x4.shared.b16 {%0,%1,%2,%3}, [%4];"
                 : "=r"(a[0]), "=r"(a[1]), "=r"(a[2]), "=r"(a[3]) : "r"(addr));
}
__device__ __forceinline__ void mma16816(float c[4], const uint32_t a[4], const uint32_t b[2]) {
    asm volatile(
        "mma.sync.aligned.m16n8k16.row.col.f32.bf16.bf16.f32 "
        "{%0,%1,%2,%3}, {%4,%5,%6,%7}, {%8,%9}, {%0,%1,%2,%3};"
        : "+f"(c[0]), "+f"(c[1]), "+f"(c[2]), "+f"(c[3])
        : "r"(a[0]), "r"(a[1]), "r"(a[2]), "r"(a[3]), "r"(b[0]), "r"(b[1]));
}

// ---------------- K1: transpose + hi/lo split + sq quarters (R15) ------------
__global__ void __launch_bounds__(128) prep_kernel(const float* __restrict__ x,
                                                   const float* __restrict__ Wfc) {
    int b = blockIdx.z;
    int cq = blockIdx.y;
    int tid = threadIdx.x;

    if (blockIdx.x == NN / 64) {
        int base = (b * 4 + cq) * 2048;
        #pragma unroll
        for (int k = 0; k < 16; k++) {
            int i = base + tid + k * 128;
            float v = Wfc[i];
            __nv_bfloat16 h = __float2bfloat16(v);
            g_Whi[i] = h;
            g_Wlo[i] = __float2bfloat16(v - __bfloat162float(h));
        }
        cudaTriggerProgrammaticLaunchCompletion();
        return;
    }

    __shared__ float tile[2][32][33];
    int n0 = blockIdx.x * 64;
    int c0 = cq * 32;
    {
        int c_local = tid >> 2, f = tid & 3;
        const float* src = x + ((size_t)b * CC + c0 + c_local) * NN + n0 + f * 8;
        float4 a0 = *(const float4*)src;
        float4 a1 = *(const float4*)(src + 4);
        float4 b0 = *(const float4*)(src + 32);
        float4 b1 = *(const float4*)(src + 36);
        tile[0][f * 8 + 0][c_local] = a0.x; tile[0][f * 8 + 1][c_local] = a0.y;
        tile[0][f * 8 + 2][c_local] = a0.z; tile[0][f * 8 + 3][c_local] = a0.w;
        tile[0][f * 8 + 4][c_local] = a1.x; tile[0][f * 8 + 5][c_local] = a1.y;
        tile[0][f * 8 + 6][c_local] = a1.z; tile[0][f * 8 + 7][c_local] = a1.w;
        tile[1][f * 8 + 0][c_local] = b0.x; tile[1][f * 8 + 1][c_local] = b0.y;
        tile[1][f * 8 + 2][c_local] = b0.z; tile[1][f * 8 + 3][c_local] = b0.w;
        tile[1][f * 8 + 4][c_local] = b1.x; tile[1][f * 8 + 5][c_local] = b1.y;
        tile[1][f * 8 + 6][c_local] = b1.z; tile[1][f * 8 + 7][c_local] = b1.w;
    }
    __syncthreads();

    int row = tid >> 2;
    int g = (tid & 3) * 8;
    #pragma unroll
    for (int sub = 0; sub < 2; sub++) {
        int nbase = n0 + sub * 32;
        float s = 0.f;
        uint32_t hw[4], lw[4];
        #pragma unroll
        for (int k = 0; k < 4; k++) {
            float v0 = tile[sub][row][g + k * 2];
            float v1 = tile[sub][row][g + k * 2 + 1];
            s += v0 * v0 + v1 * v1;
            __nv_bfloat16 h0 = __float2bfloat16(v0);
            __nv_bfloat16 h1 = __float2bfloat16(v1);
            __nv_bfloat16 l0 = __float2bfloat16(v0 - __bfloat162float(h0));
            __nv_bfloat16 l1 = __float2bfloat16(v1 - __bfloat162float(h1));
            hw[k] = (uint32_t)__bfloat16_as_ushort(h0) | ((uint32_t)__bfloat16_as_ushort(h1) << 16);
            lw[k] = (uint32_t)__bfloat16_as_ushort(l0) | ((uint32_t)__bfloat16_as_ushort(l1) << 16);
        }
        s += __shfl_xor_sync(0xffffffffu, s, 1);
        s += __shfl_xor_sync(0xffffffffu, s, 2);
        if ((tid & 3) == 0) g_sqp[cq][(size_t)b * NN + nbase + row] = s;

        size_t o = ((size_t)b * NN + nbase + row) * CC + c0 + g;
        *(uint4*)&g_xb[o] = make_uint4(hw[0], hw[1], hw[2], hw[3]);
        *(uint4*)&g_xl[o] = make_uint4(lw[0], lw[1], lw[2], lw[3]);
    }
    cudaTriggerProgrammaticLaunchCompletion();
}

// ---------------- K2: fused gemm, 512 threads (16 warps) ---------------------
#define HS_SQI 0
#define HS_SQJ 512
#define HS_A   1024
#define HS_B   33792
#define HS_H   66560
#define SH_STRIDE 144
#define YS_AH 0
#define YS_AL 16384
#define YS_WH 32768
#define YS_WL 65536
#define GM_SMEM 98304

__device__ void gemm_H_path(char* smem, int b, int tile_idx) {
    int tid = threadIdx.x;
    int wid = tid >> 5, lane = tid & 31;

    int idx = tile_idx, ti = 0, rem = 32;
    while (idx >= rem) { idx -= rem; ti++; rem--; }
    int tj = ti + idx;
    int n0 = ti * 128, m0 = tj * 128;

    float* sSqI = (float*)(smem + HS_SQI);
    float* sSqJ = (float*)(smem + HS_SQJ);
    if (tid < 128) {
        sSqI[tid] = g_sqp[0][(size_t)b * NN + n0 + tid] + g_sqp[1][(size_t)b * NN + n0 + tid]
                  + g_sqp[2][(size_t)b * NN + n0 + tid] + g_sqp[3][(size_t)b * NN + n0 + tid];
        sSqJ[tid] = g_sqp[0][(size_t)b * NN + m0 + tid] + g_sqp[1][(size_t)b * NN + m0 + tid]
                  + g_sqp[2][(size_t)b * NN + m0 + tid] + g_sqp[3][(size_t)b * NN + m0 + tid];
    }
    {
        const uint4* Ag = (const uint4*)(g_xb + ((size_t)b * NN + n0) * CC);
        const uint4* Bg = (const uint4*)(g_xb + ((size_t)b * NN + m0) * CC);
        #pragma unroll
        for (int it = 0; it < 4; it++) {
            int id = tid + it * 512;               // 0..2047
            int row = id >> 4, ch = id & 15;
            int off = row * 256 + (ch ^ (row & 7)) * 16;
            *(uint4*)(smem + HS_A + off) = Ag[(size_t)row * 16 + ch];
            *(uint4*)(smem + HS_B + off) = Bg[(size_t)row * 16 + ch];
        }
    }
    __syncthreads();

    int warp_m = wid & 3, warp_n = wid >> 2;       // 4 x 4 warps
    int mbase = warp_m * 32, nbase = warp_n * 32;

    float acc[2][4][4];
    #pragma unroll
    for (int mt = 0; mt < 2; mt++)
        #pragma unroll
        for (int nt = 0; nt < 4; nt++)
            #pragma unroll
            for (int q = 0; q < 4; q++) acc[mt][nt][q] = 0.f;

    uint32_t Abase = smem_u32(smem + HS_A);
    uint32_t Bbase = smem_u32(smem + HS_B);
    int a_row_local = lane & 15;
    int a_hi = lane >> 4;
    int bg = lane >> 3;
    int b_row_local = lane & 7;
    int b_nt_off = bg >> 1;
    int b_hi = bg & 1;

    #pragma unroll
    for (int kk = 0; kk < 8; kk++) {
        uint32_t afr[2][4];
        #pragma unroll
        for (int mt = 0; mt < 2; mt++) {
            int row = mbase + mt * 16 + a_row_local;
            int ch = (2 * kk + a_hi) ^ (row & 7);
            ldm_x4(afr[mt], Abase + row * 256 + ch * 16);
        }
        uint32_t bfr[4][2];
        #pragma unroll
        for (int nt2 = 0; nt2 < 2; nt2++) {
            int row = nbase + nt2 * 16 + b_nt_off * 8 + b_row_local;
            int ch = (2 * kk + b_hi) ^ (row & 7);
            uint32_t r4[4];
            ldm_x4(r4, Bbase + row * 256 + ch * 16);
            bfr[nt2 * 2][0] = r4[0]; bfr[nt2 * 2][1] = r4[1];
            bfr[nt2 * 2 + 1][0] = r4[2]; bfr[nt2 * 2 + 1][1] = r4[3];
        }
        #pragma unroll
        for (int mt = 0; mt < 2; mt++)
            #pragma unroll
            for (int nt = 0; nt < 4; nt++)
                mma16816(acc[mt][nt], afr[mt], bfr[nt]);
    }

    unsigned char* sH = (unsigned char*)(smem + HS_H);
    int rrow = lane >> 2;
    int ccol = (lane & 3) * 2;
    #pragma unroll
    for (int mt = 0; mt < 2; mt++) {
        #pragma unroll
        for (int nt = 0; nt < 4; nt++) {
            int col = nbase + nt * 8 + ccol;
            float sm0 = sSqJ[col], sm1 = sSqJ[col + 1];
            #pragma unroll
            for (int h = 0; h < 2; h++) {
                int row = mbase + mt * 16 + rrow + h * 8;
                float sqn = sSqI[row];
                float d20 = sqn + sm0 - 2.0f * acc[mt][nt][h * 2 + 0];
                float d21 = sqn + sm1 - 2.0f * acc[mt][nt][h * 2 + 1];
                sH[row * SH_STRIDE + col]     = (d20 < THRESH2) ? 1 : 0;
                sH[row * SH_STRIDE + col + 1] = (d21 < THRESH2) ? 1 : 0;
            }
        }
    }
    __syncthreads();

    unsigned int* Hb = g_Hb + (size_t)b * NN * (NN / 32);
    {
        int row = tid >> 2, w = tid & 3;           // 512 = 128 rows x 4 words
        const unsigned int* src = (const unsigned int*)(sH + row * SH_STRIDE + w * 32);
        unsigned int bits = 0;
        #pragma unroll
        for (int k = 0; k < 8; k++) {
            unsigned int u = src[k];
            bits |= (u & 1u) << (k * 4);
            bits |= ((u >> 8) & 1u) << (k * 4 + 1);
            bits |= ((u >> 16) & 1u) << (k * 4 + 2);
            bits |= ((u >> 24) & 1u) << (k * 4 + 3);
        }
        Hb[(size_t)(n0 + row) * (NN / 32) + (m0 >> 5) + w] = bits;
    }
    if (ti != tj && tid < 128) {
        int mrow = tid;
        unsigned int wbits[4];
        #pragma unroll
        for (int w = 0; w < 4; w++) {
            unsigned int bits = 0;
            #pragma unroll
            for (int q = 0; q < 32; q++)
                bits |= (unsigned int)(sH[(w * 32 + q) * SH_STRIDE + mrow] & 1u) << q;
            wbits[w] = bits;
        }
        *(uint4*)&Hb[(size_t)(m0 + mrow) * (NN / 32) + (n0 >> 5)] =
            make_uint4(wbits[0], wbits[1], wbits[2], wbits[3]);
    }
}

__device__ void gemm_y_path(char* smem, int b, int ytile, const float* __restrict__ bfc) {
    int tid = threadIdx.x;
    int wid = tid >> 5, lane = tid & 31;
    int n0 = ytile * 64;

    {
        const uint4* Ah = (const uint4*)(g_xb + ((size_t)b * NN + n0) * CC);
        const uint4* Al = (const uint4*)(g_xl + ((size_t)b * NN + n0) * CC);
        #pragma unroll
        for (int it = 0; it < 2; it++) {
            int id = tid + it * 512;               // 0..1023 (64 rows x 16 ch)
            int row = id >> 4, ch = id & 15;
            int off = row * 256 + (ch ^ (row & 7)) * 16;
            *(uint4*)(smem + YS_AH + off) = Ah[(size_t)row * 16 + ch];
            *(uint4*)(smem + YS_AL + off) = Al[(size_t)row * 16 + ch];
        }
        const uint4* Wh = (const uint4*)g_Whi;
        const uint4* Wl = (const uint4*)g_Wlo;
        #pragma unroll
        for (int it = 0; it < 4; it++) {
            int id = tid + it * 512;               // 0..2047
            int row = id >> 4, ch = id & 15;
            int off = row * 256 + (ch ^ (row & 7)) * 16;
            *(uint4*)(smem + YS_WH + off) = Wh[(size_t)row * 16 + ch];
            *(uint4*)(smem + YS_WL + off) = Wl[(size_t)row * 16 + ch];
        }
    }
    __syncthreads();

    int warp_m = wid & 1, warp_n = wid >> 1;       // 2 x 8 warps
    int mbase = warp_m * 32, nbase = warp_n * 16;

    float acc[2][2][4];
    #pragma unroll
    for (int mt = 0; mt < 2; mt++)
        #pragma unroll
        for (int nt = 0; nt < 2; nt++)
            #pragma unroll
            for (int q = 0; q < 4; q++) acc[mt][nt][q] = 0.f;

    int a_row_local = lane & 15;
    int a_hi = lane >> 4;
    int bg = lane >> 3;
    int b_row_local = lane & 7;
    int b_nt_off = bg >> 1;
    int b_hi = bg & 1;

    #pragma unroll
    for (int pass = 0; pass < 3; pass++) {
        uint32_t Abase = smem_u32(smem + (pass == 2 ? YS_AL : YS_AH));
        uint32_t Bbase = smem_u32(smem + (pass == 1 ? YS_WL : YS_WH));
        #pragma unroll
        for (int kk = 0; kk < 8; kk++) {
            uint32_t afr[2][4];
            #pragma unroll
            for (int mt = 0; mt < 2; mt++) {
                int row = mbase + mt * 16 + a_row_local;
                int ch = (2 * kk + a_hi) ^ (row & 7);
                ldm_x4(afr[mt], Abase + row * 256 + ch * 16);
            }
            uint32_t bfr[2][2];
            {
                int row = nbase + b_nt_off * 8 + b_row_local;
                int ch = (2 * kk + b_hi) ^ (row & 7);
                uint32_t r4[4];
                ldm_x4(r4, Bbase + row * 256 + ch * 16);
                bfr[0][0] = r4[0]; bfr[0][1] = r4[1];
                bfr[1][0] = r4[2]; bfr[1][1] = r4[3];
            }
            #pragma unroll
            for (int mt = 0; mt < 2; mt++)
                #pragma unroll
                for (int nt = 0; nt < 2; nt++)
                    mma16816(acc[mt][nt], afr[mt], bfr[nt]);
        }
    }

    int rrow = lane >> 2;
    int ccol = (lane & 3) * 2;
    float* Y = g_y + ((size_t)b * NN + n0) * CC;
    #pragma unroll
    for (int mt = 0; mt < 2; mt++) {
        #pragma unroll
        for (int nt = 0; nt < 2; nt++) {
            int col = nbase + nt * 8 + ccol;
            float b0 = bfc[col], b1 = bfc[col + 1];
            #pragma unroll
            for (int h = 0; h < 2; h++) {
                int row = mbase + mt * 16 + rrow + h * 8;
                Y[(size_t)row * CC + col]     = acc[mt][nt][h * 2 + 0] + b0;
                Y[(size_t)row * CC + col + 1] = acc[mt][nt][h * 2 + 1] + b1;
            }
        }
    }
}

__global__ void __launch_bounds__(512, 2) gemm_fused(const float* __restrict__ bfc) {
    extern __shared__ char smem[];
    int b = blockIdx.y;
    cudaGridDependencySynchronize();
    if (blockIdx.x < 528) gemm_H_path(smem, b, blockIdx.x);
    else                  gemm_y_path(smem, b, blockIdx.x - 528, bfc);
    cudaTriggerProgrammaticLaunchCompletion();
}

// ---------------- K3: mega tail (R15 body) -----------------------------------
#define TAIL_BLOCKS 512

__device__ __forceinline__ void grid_bar() {
    __syncthreads();
    if (threadIdx.x == 0) {
        __threadfence();
        unsigned int gen = *((volatile unsigned int*)&g_bargen);
        if (atomicAdd(&g_barcnt, 1u) == TAIL_BLOCKS - 1) {
            g_barcnt = 0;
            __threadfence();
            *((volatile unsigned int*)&g_bargen) = gen + 1;
        } else {
            while (*((volatile unsigned int*)&g_bargen) == gen) __nanosleep(64);
        }
    }
    __syncthreads();
}

__device__ float4 warp_gather_mean(const unsigned int* __restrict__ maskrow,
                                   unsigned short* scratch, int lane,
                                   const float* __restrict__ Ycol) {
    uint4 wv = ((const uint4*)maskrow)[lane];
    int cnt = __popc(wv.x) + __popc(wv.y) + __popc(wv.z) + __popc(wv.w);
    int pre = cnt;
    #pragma unroll
    for (int o = 1; o < 32; o <<= 1) {
        int t = __shfl_up_sync(0xffffffffu, pre, o);
        if (lane >= o) pre += t;
    }
    int deg = __shfl_sync(0xffffffffu, pre, 31);
    float4 acc = make_float4(0.f, 0.f, 0.f, 0.f);
    if (deg <= 512) {
        __syncwarp();
        int kpos = pre - cnt;
        unsigned int arr[4] = {wv.x, wv.y, wv.z, wv.w};
        #pragma unroll
        for (int j = 0; j < 4; j++) {
            unsigned int bits = arr[j];
            while (bits) {
                int q = __ffs(bits) - 1; bits &= bits - 1;
                scratch[kpos++] = (unsigned short)(lane * 128 + j * 32 + q);
            }
        }
        __syncwarp();
        for (int ii = 0; ii < deg; ii++) {
            int m = scratch[ii];
            float4 v = *(const float4*)(Ycol + (size_t)m * CC);
            acc.x += v.x; acc.y += v.y; acc.z += v.z; acc.w += v.w;
        }
    } else {
        for (int w2 = 0; w2 < NN / 32; w2++) {
            unsigned int bits = maskrow[w2];
            while (bits) {
                int q = __ffs(bits) - 1; bits &= bits - 1;
                int m = w2 * 32 + q;
                float4 v = *(const float4*)(Ycol + (size_t)m * CC);
                acc.x += v.x; acc.y += v.y; acc.z += v.z; acc.w += v.w;
            }
        }
    }
    float inv = (deg > 0) ? (1.0f / (float)deg) : 0.0f;
    return make_float4(acc.x * inv, acc.y * inv, acc.z * inv, acc.w * inv);
}

__device__ float4 compute_xout(int b, const unsigned short* list, int deg,
                               const unsigned int* __restrict__ Hrow,
                               unsigned short* scratchB, int lane,
                               const float* __restrict__ Ycol) {
    const unsigned int* Hb = g_Hb + (size_t)b * NN * (NN / 32);
    float4 acc = make_float4(0.f, 0.f, 0.f, 0.f);
    if (deg <= 512) {
        for (int k = 0; k < deg; k++) {
            int m = list[k];
            float4 Em = warp_gather_mean(Hb + (size_t)m * (NN / 32), scratchB, lane, Ycol);
            acc.x += Em.x; acc.y += Em.y; acc.z += Em.z; acc.w += Em.w;
        }
    } else {
        for (int w2 = 0; w2 < NN / 32; w2++) {
            unsigned int bits = Hrow[w2];
            while (bits) {
                int q = __ffs(bits) - 1; bits &= bits - 1;
                int m = w2 * 32 + q;
                float4 Em = warp_gather_mean(Hb + (size_t)m * (NN / 32), scratchB, lane, Ycol);
                acc.x += Em.x; acc.y += Em.y; acc.z += Em.z; acc.w += Em.w;
            }
        }
    }
    float inv = (deg > 0) ? (1.0f / (float)deg) : 0.0f;
    return make_float4(acc.x * inv, acc.y * inv, acc.z * inv, acc.w * inv);
}

__global__ void __launch_bounds__(256, 4) tail_kernel(const float* __restrict__ gamma,
                                                      const float* __restrict__ beta,
                                                      float* __restrict__ out) {
    __shared__ unsigned short sIdxA[8][2][512];
    __shared__ unsigned short sIdxB[8][512];
    __shared__ float sXe[16][CC + 4];
    __shared__ float sWPart[8][2][CC];
    __shared__ float red[2][32];

    int bx = blockIdx.x;
    int tid = threadIdx.x;
    int b = bx >> 8;
    int n0 = (bx & 255) * 16;
    int w = tid >> 5, lane = tid & 31;

    const float* Yb = g_y + (size_t)b * NN * CC;
    const float* Ycol = Yb + lane * 4;

    cudaGridDependencySynchronize();

    int n1 = n0 + w, n2 = n0 + 8 + w;
    const unsigned int* Hrow1 = g_Hb + ((size_t)b * NN + n1) * (NN / 32);
    const unsigned int* Hrow2 = g_Hb + ((size_t)b * NN + n2) * (NN / 32);
    uint4 wv1 = ((const uint4*)Hrow1)[lane];
    uint4 wv2 = ((const uint4*)Hrow2)[lane];
    int cnt1 = __popc(wv1.x) + __popc(wv1.y) + __popc(wv1.z) + __popc(wv1.w);
    int cnt2 = __popc(wv2.x) + __popc(wv2.y) + __popc(wv2.z) + __popc(wv2.w);
    int pre1 = cnt1, pre2 = cnt2;
    #pragma unroll
    for (int o = 1; o < 32; o <<= 1) {
        int t1 = __shfl_up_sync(0xffffffffu, pre1, o);
        int t2 = __shfl_up_sync(0xffffffffu, pre2, o);
        if (lane >= o) { pre1 += t1; pre2 += t2; }
    }
    int deg1 = __shfl_sync(0xffffffffu, pre1, 31);
    int deg2 = __shfl_sync(0xffffffffu, pre2, 31);
    if (deg1 <= 512) {
        int kpos = pre1 - cnt1;
        unsigned int arr1[4] = {wv1.x, wv1.y, wv1.z, wv1.w};
        #pragma unroll
        for (int j = 0; j < 4; j++) {
            unsigned int bits = arr1[j];
            while (bits) {
                int q = __ffs(bits) - 1; bits &= bits - 1;
                sIdxA[w][0][kpos++] = (unsigned short)(lane * 128 + j * 32 + q);
            }
        }
    }
    if (deg2 <= 512) {
        int kpos = pre2 - cnt2;
        unsigned int arr2[4] = {wv2.x, wv2.y, wv2.z, wv2.w};
        #pragma unroll
        for (int j = 0; j < 4; j++) {
            unsigned int bits = arr2[j];
            while (bits) {
                int q = __ffs(bits) - 1; bits &= bits - 1;
                sIdxA[w][1][kpos++] = (unsigned short)(lane * 128 + j * 32 + q);
            }
        }
    }
    __syncwarp();

    float4 y1 = *(const float4*)(Ycol + (size_t)n1 * CC);
    float4 y2 = *(const float4*)(Ycol + (size_t)n2 * CC);

    float4 xo1, xo2;
    if (deg1 == 1) { xo1 = y1; }
    else { xo1 = compute_xout(b, sIdxA[w][0], deg1, Hrow1, sIdxB[w], lane, Ycol); }
    if (deg2 == 1) { xo2 = y2; }
    else { xo2 = compute_xout(b, sIdxA[w][1], deg2, Hrow2, sIdxB[w], lane, Ycol); }

    float4 xe1 = make_float4(y1.x + xo1.x, y1.y + xo1.y, y1.z + xo1.z, y1.w + xo1.w);
    float4 xe2 = make_float4(y2.x + xo2.x, y2.y + xo2.y, y2.z + xo2.z, y2.w + xo2.w);
    *(float4*)&sXe[w][lane * 4]     = xe1;
    *(float4*)&sXe[8 + w][lane * 4] = xe2;

    float4 ps = make_float4(xe1.x + xe2.x, xe1.y + xe2.y, xe1.z + xe2.z, xe1.w + xe2.w);
    float4 ps2 = make_float4(xe1.x * xe1.x + xe2.x * xe2.x,
                             xe1.y * xe1.y + xe2.y * xe2.y,
                             xe1.z * xe1.z + xe2.z * xe2.z,
                             xe1.w * xe1.w + xe2.w * xe2.w);
    {
        sWPart[w][0][lane * 4 + 0] = ps.x;  sWPart[w][0][lane * 4 + 1] = ps.y;
        sWPart[w][0][lane * 4 + 2] = ps.z;  sWPart[w][0][lane * 4 + 3] = ps.w;
        sWPart[w][1][lane * 4 + 0] = ps2.x; sWPart[w][1][lane * 4 + 1] = ps2.y;
        sWPart[w][1][lane * 4 + 2] = ps2.z; sWPart[w][1][lane * 4 + 3] = ps2.w;
        __syncthreads();
        int c = tid & 127, which = tid >> 7;
        float s = 0.f;
        #pragma unroll
        for (int k = 0; k < 8; k++) s += sWPart[k][which][c];
        g_partT[which][c][bx] = s;
    }
    grid_bar();
    if (bx < CC) {
        int ch = bx;
        float s = 0.f, s2 = 0.f;
        #pragma unroll
        for (int k = 0; k < 2; k++) {
            int slot = tid + k * 256;
            s  += __ldcg(&g_partT[0][ch][slot]);
            s2 += __ldcg(&g_partT[1][ch][slot]);
        }
        #pragma unroll
        for (int o = 16; o > 0; o >>= 1) {
            s  += __shfl_xor_sync(0xffffffffu, s,  o);
            s2 += __shfl_xor_sync(0xffffffffu, s2, o);
        }
        if (lane == 0) { red[0][w] = s; red[1][w] = s2; }
        __syncthreads();
        if (tid == 0) {
            float ts = 0.f, ts2 = 0.f;
            #pragma unroll
            for (int k = 0; k < 8; k++) { ts += red[0][k]; ts2 += red[1][k]; }
            float mean = ts / (float)(BB * NN);
            float var = ts2 / (float)(BB * NN) - mean * mean;
            g_mean[ch] = mean;
            g_rstd[ch] = rsqrtf(var + BN_EPS);
        }
    }
    grid_bar();
    {
        int c = tid >> 1;
        int half = tid & 1;
        float mean = __ldcg(&g_mean[c]);
        float rstd = __ldcg(&g_rstd[c]);
        float ga = gamma[c], be = beta[c];
        float vout[8];
        #pragma unroll
        for (int k = 0; k < 8; k++) {
            float v = sXe[half * 8 + k][c];
            float xn = ga * ((v - mean) * rstd) + be;
            float sig = 1.0f / (1.0f + expf(-xn));
            vout[k] = xn * sig;
        }
        float* dst = out + ((size_t)b * CC + c) * NN + n0 + half * 8;
        *(float4*)dst       = make_float4(vout[0], vout[1], vout[2], vout[3]);
        *(float4*)(dst + 4) = make_float4(vout[4], vout[5], vout[6], vout[7]);
    }
}

// ---------------- entry ------------------------------------------------------
extern "C" void kernel_launch(void* const* d_in, const int* in_sizes, int n_in,
                              void* d_out, int out_size) {
    const float* x     = (const float*)d_in[0];
    const float* Wfc   = (const float*)d_in[1];
    const float* bfc   = (const float*)d_in[2];
    const float* gamma = (const float*)d_in[3];
    const float* beta  = (const float*)d_in[4];
    float* out = (float*)d_out;

    cudaFuncSetAttribute(gemm_fused, cudaFuncAttributeMaxDynamicSharedMemorySize, GM_SMEM);

    prep_kernel<<<dim3(NN / 64 + 1, 4, BB), 128>>>(x, Wfc);

    {
        cudaLaunchConfig_t cfg = {};
        cfg.gridDim = dim3(592, BB, 1);
        cfg.blockDim = dim3(512, 1, 1);
        cfg.dynamicSmemBytes = GM_SMEM;
        cfg.stream = 0;
        cudaLaunchAttribute attr[1];
        attr[0].id = cudaLaunchAttributeProgrammaticStreamSerialization;
        attr[0].val.programmaticStreamSerializationAllowed = 1;
        cfg.attrs = attr;
        cfg.numAttrs = 1;
        cudaLaunchKernelEx(&cfg, gemm_fused, bfc);
    }
    {
        cudaLaunchConfig_t cfg = {};
        cfg.gridDim = dim3(TAIL_BLOCKS, 1, 1);
        cfg.blockDim = dim3(256, 1, 1);
        cfg.dynamicSmemBytes = 0;
        cfg.stream = 0;
        cudaLaunchAttribute attr[1];
        attr[0].id = cudaLaunchAttributeProgrammaticStreamSerialization;
        attr[0].val.programmaticStreamSerializationAllowed = 1;
        cfg.attrs = attr;
        cfg.numAttrs = 1;
        cudaLaunchKernelEx(&cfg, tail_kernel, gamma, beta, out);
    }
}

// round 17
// speedup vs baseline: 2.1484x; 2.1484x over previous
#include <cuda_runtime.h>
#include <cuda_bf16.h>
#include <cstdint>

#define BB 2
#define CC 128
#define NN 4096
#define THRESH2 64.0f
#define BN_EPS 1e-5f

// ---------------- scratch (device globals) -----------------------------------
__device__ __nv_bfloat16 g_xb[BB * NN * CC];
__device__ __nv_bfloat16 g_xl[BB * NN * CC];
__device__ __nv_bfloat16 g_Whi[CC * CC];
__device__ __nv_bfloat16 g_Wlo[CC * CC];
__device__ float g_sqp[4][BB * NN];
__device__ float g_y [BB * NN * CC];
__device__ unsigned int g_Hb[(size_t)BB * NN * (NN / 32)];
__device__ float g_partT[2][CC][512];
__device__ float g_mean[CC];
__device__ float g_rstd[CC];
__device__ unsigned int g_barcnt = 0;
__device__ unsigned int g_bargen = 0;

__device__ __forceinline__ uint32_t smem_u32(const void* p) {
    uint32_t a;
    asm("{ .reg .u64 t; cvta.to.shared.u64 t, %1; cvt.u32.u64 %0, t; }" : "=r"(a) : "l"(p));
    return a;
}
__device__ __forceinline__ void ldm_x4(uint32_t a[4], uint32_t addr) {
    asm volatile("ldmatrix.sync.aligned.m8n8.x4.shared.b16 {%0,%1,%2,%3}, [%4];"
                 : "=r"(a[0]), "=r"(a[1]), "=r"(a[2]), "=r"(a[3]) : "r"(addr));
}
__device__ __forceinline__ void mma16816(float c[4], const uint32_t a[4], const uint32_t b[2]) {
    asm volatile(
        "mma.sync.aligned.m16n8k16.row.col.f32.bf16.bf16.f32 "
        "{%0,%1,%2,%3}, {%4,%5,%6,%7}, {%8,%9}, {%0,%1,%2,%3};"
        : "+f"(c[0]), "+f"(c[1]), "+f"(c[2]), "+f"(c[3])
        : "r"(a[0]), "r"(a[1]), "r"(a[2]), "r"(a[3]), "r"(b[0]), "r"(b[1]));
}

// ---------------- K1: transpose + hi/lo split + sq quarters ------------------
__global__ void __launch_bounds__(128) prep_kernel(const float* __restrict__ x,
                                                   const float* __restrict__ Wfc) {
    int b = blockIdx.z;
    int cq = blockIdx.y;
    int tid = threadIdx.x;

    if (blockIdx.x == NN / 64) {               // W split: 8 blocks x 2048 elems
        int base = (b * 4 + cq) * 2048;
        #pragma unroll
        for (int k = 0; k < 16; k++) {
            int i = base + tid + k * 128;
            float v = Wfc[i];
            __nv_bfloat16 h = __float2bfloat16(v);
            g_Whi[i] = h;
            g_Wlo[i] = __float2bfloat16(v - __bfloat162float(h));
        }
        cudaTriggerProgrammaticLaunchCompletion();
        return;
    }

    __shared__ float tile[2][32][33];
    int n0 = blockIdx.x * 64;
    int c0 = cq * 32;
    {
        int c_local = tid >> 2, f = tid & 3;
        const float* src = x + ((size_t)b * CC + c0 + c_local) * NN + n0 + f * 8;
        float4 a0 = *(const float4*)src;
        float4 a1 = *(const float4*)(src + 4);
        float4 b0 = *(const float4*)(src + 32);
        float4 b1 = *(const float4*)(src + 36);
        tile[0][f * 8 + 0][c_local] = a0.x; tile[0][f * 8 + 1][c_local] = a0.y;
        tile[0][f * 8 + 2][c_local] = a0.z; tile[0][f * 8 + 3][c_local] = a0.w;
        tile[0][f * 8 + 4][c_local] = a1.x; tile[0][f * 8 + 5][c_local] = a1.y;
        tile[0][f * 8 + 6][c_local] = a1.z; tile[0][f * 8 + 7][c_local] = a1.w;
        tile[1][f * 8 + 0][c_local] = b0.x; tile[1][f * 8 + 1][c_local] = b0.y;
        tile[1][f * 8 + 2][c_local] = b0.z; tile[1][f * 8 + 3][c_local] = b0.w;
        tile[1][f * 8 + 4][c_local] = b1.x; tile[1][f * 8 + 5][c_local] = b1.y;
        tile[1][f * 8 + 6][c_local] = b1.z; tile[1][f * 8 + 7][c_local] = b1.w;
    }
    __syncthreads();

    int row = tid >> 2;
    int g = (tid & 3) * 8;
    #pragma unroll
    for (int sub = 0; sub < 2; sub++) {
        int nbase = n0 + sub * 32;
        float s = 0.f;
        uint32_t hw[4], lw[4];
        #pragma unroll
        for (int k = 0; k < 4; k++) {
            float v0 = tile[sub][row][g + k * 2];
            float v1 = tile[sub][row][g + k * 2 + 1];
            s += v0 * v0 + v1 * v1;
            __nv_bfloat16 h0 = __float2bfloat16(v0);
            __nv_bfloat16 h1 = __float2bfloat16(v1);
            __nv_bfloat16 l0 = __float2bfloat16(v0 - __bfloat162float(h0));
            __nv_bfloat16 l1 = __float2bfloat16(v1 - __bfloat162float(h1));
            hw[k] = (uint32_t)__bfloat16_as_ushort(h0) | ((uint32_t)__bfloat16_as_ushort(h1) << 16);
            lw[k] = (uint32_t)__bfloat16_as_ushort(l0) | ((uint32_t)__bfloat16_as_ushort(l1) << 16);
        }
        s += __shfl_xor_sync(0xffffffffu, s, 1);
        s += __shfl_xor_sync(0xffffffffu, s, 2);
        if ((tid & 3) == 0) g_sqp[cq][(size_t)b * NN + nbase + row] = s;

        size_t o = ((size_t)b * NN + nbase + row) * CC + c0 + g;
        *(uint4*)&g_xb[o] = make_uint4(hw[0], hw[1], hw[2], hw[3]);
        *(uint4*)&g_xl[o] = make_uint4(lw[0], lw[1], lw[2], lw[3]);
    }
    cudaTriggerProgrammaticLaunchCompletion();
}

// ---------------- K2: fused gemm (R10 bodies) --------------------------------
#define HS_SQI 0
#define HS_SQJ 512
#define HS_A   1024
#define HS_B   33792
#define HS_H   66560
#define SH_STRIDE 144
#define YS_AH 0
#define YS_AL 16384
#define YS_WH 32768
#define YS_WL 65536
#define GM_SMEM 98304

__device__ void gemm_H_path(char* smem, int b, int tile_idx) {
    int tid = threadIdx.x;
    int wid = tid >> 5, lane = tid & 31;

    int idx = tile_idx, ti = 0, rem = 32;
    while (idx >= rem) { idx -= rem; ti++; rem--; }
    int tj = ti + idx;
    int n0 = ti * 128, m0 = tj * 128;

    float* sSqI = (float*)(smem + HS_SQI);
    float* sSqJ = (float*)(smem + HS_SQJ);
    if (tid < 128) {
        sSqI[tid] = g_sqp[0][(size_t)b * NN + n0 + tid] + g_sqp[1][(size_t)b * NN + n0 + tid]
                  + g_sqp[2][(size_t)b * NN + n0 + tid] + g_sqp[3][(size_t)b * NN + n0 + tid];
        sSqJ[tid] = g_sqp[0][(size_t)b * NN + m0 + tid] + g_sqp[1][(size_t)b * NN + m0 + tid]
                  + g_sqp[2][(size_t)b * NN + m0 + tid] + g_sqp[3][(size_t)b * NN + m0 + tid];
    }
    {
        const uint4* Ag = (const uint4*)(g_xb + ((size_t)b * NN + n0) * CC);
        const uint4* Bg = (const uint4*)(g_xb + ((size_t)b * NN + m0) * CC);
        #pragma unroll
        for (int it = 0; it < 8; it++) {
            int id = tid + it * 256;
            int row = id >> 4, ch = id & 15;
            int off = row * 256 + (ch ^ (row & 7)) * 16;
            *(uint4*)(smem + HS_A + off) = Ag[(size_t)row * 16 + ch];
            *(uint4*)(smem + HS_B + off) = Bg[(size_t)row * 16 + ch];
        }
    }
    __syncthreads();

    int warp_m = wid & 3, warp_n = wid >> 2;
    int mbase = warp_m * 32, nbase = warp_n * 64;

    float acc[2][8][4];
    #pragma unroll
    for (int mt = 0; mt < 2; mt++)
        #pragma unroll
        for (int nt = 0; nt < 8; nt++)
            #pragma unroll
            for (int q = 0; q < 4; q++) acc[mt][nt][q] = 0.f;

    uint32_t Abase = smem_u32(smem + HS_A);
    uint32_t Bbase = smem_u32(smem + HS_B);
    int a_row_local = lane & 15;
    int a_hi = lane >> 4;
    int bg = lane >> 3;
    int b_row_local = lane & 7;
    int b_nt_off = bg >> 1;
    int b_hi = bg & 1;

    #pragma unroll
    for (int kk = 0; kk < 8; kk++) {
        uint32_t afr[2][4];
        #pragma unroll
        for (int mt = 0; mt < 2; mt++) {
            int row = mbase + mt * 16 + a_row_local;
            int ch = (2 * kk + a_hi) ^ (row & 7);
            ldm_x4(afr[mt], Abase + row * 256 + ch * 16);
        }
        uint32_t bfr[8][2];
        #pragma unroll
        for (int nt2 = 0; nt2 < 4; nt2++) {
            int row = nbase + nt2 * 16 + b_nt_off * 8 + b_row_local;
            int ch = (2 * kk + b_hi) ^ (row & 7);
            uint32_t r4[4];
            ldm_x4(r4, Bbase + row * 256 + ch * 16);
            bfr[nt2 * 2][0] = r4[0]; bfr[nt2 * 2][1] = r4[1];
            bfr[nt2 * 2 + 1][0] = r4[2]; bfr[nt2 * 2 + 1][1] = r4[3];
        }
        #pragma unroll
        for (int mt = 0; mt < 2; mt++)
            #pragma unroll
            for (int nt = 0; nt < 8; nt++)
                mma16816(acc[mt][nt], afr[mt], bfr[nt]);
    }

    unsigned char* sH = (unsigned char*)(smem + HS_H);
    int rrow = lane >> 2;
    int ccol = (lane & 3) * 2;
    #pragma unroll
    for (int mt = 0; mt < 2; mt++) {
        #pragma unroll
        for (int nt = 0; nt < 8; nt++) {
            int col = nbase + nt * 8 + ccol;
            float sm0 = sSqJ[col], sm1 = sSqJ[col + 1];
            #pragma unroll
            for (int h = 0; h < 2; h++) {
                int row = mbase + mt * 16 + rrow + h * 8;
                float sqn = sSqI[row];
                float d20 = sqn + sm0 - 2.0f * acc[mt][nt][h * 2 + 0];
                float d21 = sqn + sm1 - 2.0f * acc[mt][nt][h * 2 + 1];
                sH[row * SH_STRIDE + col]     = (d20 < THRESH2) ? 1 : 0;
                sH[row * SH_STRIDE + col + 1] = (d21 < THRESH2) ? 1 : 0;
            }
        }
    }
    __syncthreads();

    unsigned int* Hb = g_Hb + (size_t)b * NN * (NN / 32);
    #pragma unroll
    for (int it = 0; it < 2; it++) {
        int id = tid + it * 256;
        int row = id >> 2, w = id & 3;
        const unsigned int* src = (const unsigned int*)(sH + row * SH_STRIDE + w * 32);
        unsigned int bits = 0;
        #pragma unroll
        for (int k = 0; k < 8; k++) {
            unsigned int u = src[k];
            bits |= (u & 1u) << (k * 4);
            bits |= ((u >> 8) & 1u) << (k * 4 + 1);
            bits |= ((u >> 16) & 1u) << (k * 4 + 2);
            bits |= ((u >> 24) & 1u) << (k * 4 + 3);
        }
        Hb[(size_t)(n0 + row) * (NN / 32) + (m0 >> 5) + w] = bits;
    }
    if (ti != tj && tid < 128) {
        int mrow = tid;
        unsigned int wbits[4];
        #pragma unroll
        for (int w = 0; w < 4; w++) {
            unsigned int bits = 0;
            #pragma unroll
            for (int q = 0; q < 32; q++)
                bits |= (unsigned int)(sH[(w * 32 + q) * SH_STRIDE + mrow] & 1u) << q;
            wbits[w] = bits;
        }
        *(uint4*)&Hb[(size_t)(m0 + mrow) * (NN / 32) + (n0 >> 5)] =
            make_uint4(wbits[0], wbits[1], wbits[2], wbits[3]);
    }
}

__device__ void gemm_y_path(char* smem, int b, int ytile, const float* __restrict__ bfc) {
    int tid = threadIdx.x;
    int wid = tid >> 5, lane = tid & 31;
    int n0 = ytile * 64;

    {
        const uint4* Ah = (const uint4*)(g_xb + ((size_t)b * NN + n0) * CC);
        const uint4* Al = (const uint4*)(g_xl + ((size_t)b * NN + n0) * CC);
        #pragma unroll
        for (int it = 0; it < 4; it++) {
            int id = tid + it * 256;
            int row = id >> 4, ch = id & 15;
            int off = row * 256 + (ch ^ (row & 7)) * 16;
            *(uint4*)(smem + YS_AH + off) = Ah[(size_t)row * 16 + ch];
            *(uint4*)(smem + YS_AL + off) = Al[(size_t)row * 16 + ch];
        }
        const uint4* Wh = (const uint4*)g_Whi;
        const uint4* Wl = (const uint4*)g_Wlo;
        #pragma unroll
        for (int it = 0; it < 8; it++) {
            int id = tid + it * 256;
            int row = id >> 4, ch = id & 15;
            int off = row * 256 + (ch ^ (row & 7)) * 16;
            *(uint4*)(smem + YS_WH + off) = Wh[(size_t)row * 16 + ch];
            *(uint4*)(smem + YS_WL + off) = Wl[(size_t)row * 16 + ch];
        }
    }
    __syncthreads();

    int warp_m = wid & 1, warp_n = wid >> 1;
    int mbase = warp_m * 32, nbase = warp_n * 32;

    float acc[2][4][4];
    #pragma unroll
    for (int mt = 0; mt < 2; mt++)
        #pragma unroll
        for (int nt = 0; nt < 4; nt++)
            #pragma unroll
            for (int q = 0; q < 4; q++) acc[mt][nt][q] = 0.f;

    int a_row_local = lane & 15;
    int a_hi = lane >> 4;
    int bg = lane >> 3;
    int b_row_local = lane & 7;
    int b_nt_off = bg >> 1;
    int b_hi = bg & 1;

    #pragma unroll
    for (int pass = 0; pass < 3; pass++) {
        uint32_t Abase = smem_u32(smem + (pass == 2 ? YS_AL : YS_AH));
        uint32_t Bbase = smem_u32(smem + (pass == 1 ? YS_WL : YS_WH));
        #pragma unroll
        for (int kk = 0; kk < 8; kk++) {
            uint32_t afr[2][4];
            #pragma unroll
            for (int mt = 0; mt < 2; mt++) {
                int row = mbase + mt * 16 + a_row_local;
                int ch = (2 * kk + a_hi) ^ (row & 7);
                ldm_x4(afr[mt], Abase + row * 256 + ch * 16);
            }
            uint32_t bfr[4][2];
            #pragma unroll
            for (int nt2 = 0; nt2 < 2; nt2++) {
                int row = nbase + nt2 * 16 + b_nt_off * 8 + b_row_local;
                int ch = (2 * kk + b_hi) ^ (row & 7);
                uint32_t r4[4];
                ldm_x4(r4, Bbase + row * 256 + ch * 16);
                bfr[nt2 * 2][0] = r4[0]; bfr[nt2 * 2][1] = r4[1];
                bfr[nt2 * 2 + 1][0] = r4[2]; bfr[nt2 * 2 + 1][1] = r4[3];
            }
            #pragma unroll
            for (int mt = 0; mt < 2; mt++)
                #pragma unroll
                for (int nt = 0; nt < 4; nt++)
                    mma16816(acc[mt][nt], afr[mt], bfr[nt]);
        }
    }

    int rrow = lane >> 2;
    int ccol = (lane & 3) * 2;
    float* Y = g_y + ((size_t)b * NN + n0) * CC;
    #pragma unroll
    for (int mt = 0; mt < 2; mt++) {
        #pragma unroll
        for (int nt = 0; nt < 4; nt++) {
            int col = nbase + nt * 8 + ccol;
            float b0 = bfc[col], b1 = bfc[col + 1];
            #pragma unroll
            for (int h = 0; h < 2; h++) {
                int row = mbase + mt * 16 + rrow + h * 8;
                Y[(size_t)row * CC + col]     = acc[mt][nt][h * 2 + 0] + b0;
                Y[(size_t)row * CC + col + 1] = acc[mt][nt][h * 2 + 1] + b1;
            }
        }
    }
}

__global__ void __launch_bounds__(256, 2) gemm_fused(const float* __restrict__ bfc) {
    extern __shared__ char smem[];
    int b = blockIdx.y;
    cudaGridDependencySynchronize();           // wait for prep's writes
    if (blockIdx.x < 528) gemm_H_path(smem, b, blockIdx.x);
    else                  gemm_y_path(smem, b, blockIdx.x - 528, bfc);
    cudaTriggerProgrammaticLaunchCompletion();
}

// ---------------- K3: mega tail (R10 bodies) ---------------------------------
#define TAIL_BLOCKS 512

__device__ __forceinline__ void grid_bar() {
    __syncthreads();
    if (threadIdx.x == 0) {
        __threadfence();
        unsigned int gen = *((volatile unsigned int*)&g_bargen);
        if (atomicAdd(&g_barcnt, 1u) == TAIL_BLOCKS - 1) {
            g_barcnt = 0;
            __threadfence();
            *((volatile unsigned int*)&g_bargen) = gen + 1;
        } else {
            while (*((volatile unsigned int*)&g_bargen) == gen) __nanosleep(64);
        }
    }
    __syncthreads();
}

__device__ float4 warp_gather_mean(const unsigned int* __restrict__ maskrow,
                                   unsigned short* scratch, int lane,
                                   const float* __restrict__ Ycol) {
    uint4 wv = ((const uint4*)maskrow)[lane];
    int cnt = __popc(wv.x) + __popc(wv.y) + __popc(wv.z) + __popc(wv.w);
    int pre = cnt;
    #pragma unroll
    for (int o = 1; o < 32; o <<= 1) {
        int t = __shfl_up_sync(0xffffffffu, pre, o);
        if (lane >= o) pre += t;
    }
    int deg = __shfl_sync(0xffffffffu, pre, 31);
    float4 acc = make_float4(0.f, 0.f, 0.f, 0.f);
    if (deg <= 512) {
        __syncwarp();
        int kpos = pre - cnt;
        unsigned int arr[4] = {wv.x, wv.y, wv.z, wv.w};
        #pragma unroll
        for (int j = 0; j < 4; j++) {
            unsigned int bits = arr[j];
            while (bits) {
                int q = __ffs(bits) - 1; bits &= bits - 1;
                scratch[kpos++] = (unsigned short)(lane * 128 + j * 32 + q);
            }
        }
        __syncwarp();
        for (int ii = 0; ii < deg; ii++) {
            int m = scratch[ii];
            float4 v = *(const float4*)(Ycol + (size_t)m * CC);
            acc.x += v.x; acc.y += v.y; acc.z += v.z; acc.w += v.w;
        }
    } else {
        for (int w2 = 0; w2 < NN / 32; w2++) {
            unsigned int bits = maskrow[w2];
            while (bits) {
                int q = __ffs(bits) - 1; bits &= bits - 1;
                int m = w2 * 32 + q;
                float4 v = *(const float4*)(Ycol + (size_t)m * CC);
                acc.x += v.x; acc.y += v.y; acc.z += v.z; acc.w += v.w;
            }
        }
    }
    float inv = (deg > 0) ? (1.0f / (float)deg) : 0.0f;
    return make_float4(acc.x * inv, acc.y * inv, acc.z * inv, acc.w * inv);
}

__device__ float4 compute_xout(int b, const unsigned short* list, int deg,
                               const unsigned int* __restrict__ Hrow,
                               unsigned short* scratchB, int lane,
                               const float* __restrict__ Ycol) {
    const unsigned int* Hb = g_Hb + (size_t)b * NN * (NN / 32);
    float4 acc = make_float4(0.f, 0.f, 0.f, 0.f);
    if (deg <= 512) {
        for (int k = 0; k < deg; k++) {
            int m = list[k];
            float4 Em = warp_gather_mean(Hb + (size_t)m * (NN / 32), scratchB, lane, Ycol);
            acc.x += Em.x; acc.y += Em.y; acc.z += Em.z; acc.w += Em.w;
        }
    } else {
        for (int w2 = 0; w2 < NN / 32; w2++) {
            unsigned int bits = Hrow[w2];
            while (bits) {
                int q = __ffs(bits) - 1; bits &= bits - 1;
                int m = w2 * 32 + q;
                float4 Em = warp_gather_mean(Hb + (size_t)m * (NN / 32), scratchB, lane, Ycol);
                acc.x += Em.x; acc.y += Em.y; acc.z += Em.z; acc.w += Em.w;
            }
        }
    }
    float inv = (deg > 0) ? (1.0f / (float)deg) : 0.0f;
    return make_float4(acc.x * inv, acc.y * inv, acc.z * inv, acc.w * inv);
}

__global__ void __launch_bounds__(256, 4) tail_kernel(const float* __restrict__ gamma,
                                                      const float* __restrict__ beta,
                                                      float* __restrict__ out) {
    __shared__ unsigned short sIdxA[8][2][512];
    __shared__ unsigned short sIdxB[8][512];
    __shared__ float sXe[16][CC + 4];
    __shared__ float sWPart[8][2][CC];
    __shared__ float red[2][32];

    int bx = blockIdx.x;
    int tid = threadIdx.x;
    int b = bx >> 8;
    int n0 = (bx & 255) * 16;
    int w = tid >> 5, lane = tid & 31;

    const float* Yb = g_y + (size_t)b * NN * CC;
    const float* Ycol = Yb + lane * 4;

    cudaGridDependencySynchronize();           // wait for gemm's writes

    int n1 = n0 + w, n2 = n0 + 8 + w;
    const unsigned int* Hrow1 = g_Hb + ((size_t)b * NN + n1) * (NN / 32);
    const unsigned int* Hrow2 = g_Hb + ((size_t)b * NN + n2) * (NN / 32);
    uint4 wv1 = ((const uint4*)Hrow1)[lane];
    uint4 wv2 = ((const uint4*)Hrow2)[lane];
    int cnt1 = __popc(wv1.x) + __popc(wv1.y) + __popc(wv1.z) + __popc(wv1.w);
    int cnt2 = __popc(wv2.x) + __popc(wv2.y) + __popc(wv2.z) + __popc(wv2.w);
    int pre1 = cnt1, pre2 = cnt2;
    #pragma unroll
    for (int o = 1; o < 32; o <<= 1) {
        int t1 = __shfl_up_sync(0xffffffffu, pre1, o);
        int t2 = __shfl_up_sync(0xffffffffu, pre2, o);
        if (lane >= o) { pre1 += t1; pre2 += t2; }
    }
    int deg1 = __shfl_sync(0xffffffffu, pre1, 31);
    int deg2 = __shfl_sync(0xffffffffu, pre2, 31);
    if (deg1 <= 512) {
        int kpos = pre1 - cnt1;
        unsigned int arr1[4] = {wv1.x, wv1.y, wv1.z, wv1.w};
        #pragma unroll
        for (int j = 0; j < 4; j++) {
            unsigned int bits = arr1[j];
            while (bits) {
                int q = __ffs(bits) - 1; bits &= bits - 1;
                sIdxA[w][0][kpos++] = (unsigned short)(lane * 128 + j * 32 + q);
            }
        }
    }
    if (deg2 <= 512) {
        int kpos = pre2 - cnt2;
        unsigned int arr2[4] = {wv2.x, wv2.y, wv2.z, wv2.w};
        #pragma unroll
        for (int j = 0; j < 4; j++) {
            unsigned int bits = arr2[j];
            while (bits) {
                int q = __ffs(bits) - 1; bits &= bits - 1;
                sIdxA[w][1][kpos++] = (unsigned short)(lane * 128 + j * 32 + q);
            }
        }
    }
    __syncwarp();

    float4 y1 = *(const float4*)(Ycol + (size_t)n1 * CC);
    float4 y2 = *(const float4*)(Ycol + (size_t)n2 * CC);

    float4 xo1, xo2;
    if (deg1 == 1) { xo1 = y1; }
    else { xo1 = compute_xout(b, sIdxA[w][0], deg1, Hrow1, sIdxB[w], lane, Ycol); }
    if (deg2 == 1) { xo2 = y2; }
    else { xo2 = compute_xout(b, sIdxA[w][1], deg2, Hrow2, sIdxB[w], lane, Ycol); }

    float4 xe1 = make_float4(y1.x + xo1.x, y1.y + xo1.y, y1.z + xo1.z, y1.w + xo1.w);
    float4 xe2 = make_float4(y2.x + xo2.x, y2.y + xo2.y, y2.z + xo2.z, y2.w + xo2.w);
    *(float4*)&sXe[w][lane * 4]     = xe1;
    *(float4*)&sXe[8 + w][lane * 4] = xe2;

    float4 ps = make_float4(xe1.x + xe2.x, xe1.y + xe2.y, xe1.z + xe2.z, xe1.w + xe2.w);
    float4 ps2 = make_float4(xe1.x * xe1.x + xe2.x * xe2.x,
                             xe1.y * xe1.y + xe2.y * xe2.y,
                             xe1.z * xe1.z + xe2.z * xe2.z,
                             xe1.w * xe1.w + xe2.w * xe2.w);
    {
        sWPart[w][0][lane * 4 + 0] = ps.x;  sWPart[w][0][lane * 4 + 1] = ps.y;
        sWPart[w][0][lane * 4 + 2] = ps.z;  sWPart[w][0][lane * 4 + 3] = ps.w;
        sWPart[w][1][lane * 4 + 0] = ps2.x; sWPart[w][1][lane * 4 + 1] = ps2.y;
        sWPart[w][1][lane * 4 + 2] = ps2.z; sWPart[w][1][lane * 4 + 3] = ps2.w;
        __syncthreads();
        int c = tid & 127, which = tid >> 7;
        float s = 0.f;
        #pragma unroll
        for (int k = 0; k < 8; k++) s += sWPart[k][which][c];
        g_partT[which][c][bx] = s;
    }
    grid_bar();
    if (bx < CC) {
        int ch = bx;
        float s = 0.f, s2 = 0.f;
        #pragma unroll
        for (int k = 0; k < 2; k++) {
            int slot = tid + k * 256;
            s  += __ldcg(&g_partT[0][ch][slot]);
            s2 += __ldcg(&g_partT[1][ch][slot]);
        }
        #pragma unroll
        for (int o = 16; o > 0; o >>= 1) {
            s  += __shfl_xor_sync(0xffffffffu, s,  o);
            s2 += __shfl_xor_sync(0xffffffffu, s2, o);
        }
        if (lane == 0) { red[0][w] = s; red[1][w] = s2; }
        __syncthreads();
        if (tid == 0) {
            float ts = 0.f, ts2 = 0.f;
            #pragma unroll
            for (int k = 0; k < 8; k++) { ts += red[0][k]; ts2 += red[1][k]; }
            float mean = ts / (float)(BB * NN);
            float var = ts2 / (float)(BB * NN) - mean * mean;
            g_mean[ch] = mean;
            g_rstd[ch] = rsqrtf(var + BN_EPS);
        }
    }
    grid_bar();
    {
        int c = tid >> 1;
        int half = tid & 1;
        float mean = __ldcg(&g_mean[c]);
        float rstd = __ldcg(&g_rstd[c]);
        float ga = gamma[c], be = beta[c];
        float vout[8];
        #pragma unroll
        for (int k = 0; k < 8; k++) {
            float v = sXe[half * 8 + k][c];
            float xn = ga * ((v - mean) * rstd) + be;
            float sig = 1.0f / (1.0f + expf(-xn));
            vout[k] = xn * sig;
        }
        float* dst = out + ((size_t)b * CC + c) * NN + n0 + half * 8;
        *(float4*)dst       = make_float4(vout[0], vout[1], vout[2], vout[3]);
        *(float4*)(dst + 4) = make_float4(vout[4], vout[5], vout[6], vout[7]);
    }
}

// ---------------- entry ------------------------------------------------------
extern "C" void kernel_launch(void* const* d_in, const int* in_sizes, int n_in,
                              void* d_out, int out_size) {
    const float* x     = (const float*)d_in[0];
    const float* Wfc   = (const float*)d_in[1];
    const float* bfc   = (const float*)d_in[2];
    const float* gamma = (const float*)d_in[3];
    const float* beta  = (const float*)d_in[4];
    float* out = (float*)d_out;

    cudaFuncSetAttribute(gemm_fused, cudaFuncAttributeMaxDynamicSharedMemorySize, GM_SMEM);

    // K1: plain launch
    prep_kernel<<<dim3(NN / 64 + 1, 4, BB), 128>>>(x, Wfc);

    // K2: PDL launch (overlaps with prep's drain)
    {
        cudaLaunchConfig_t cfg = {};
        cfg.gridDim = dim3(592, BB, 1);
        cfg.blockDim = dim3(256, 1, 1);
        cfg.dynamicSmemBytes = GM_SMEM;
        cfg.stream = 0;
        cudaLaunchAttribute attr[1];
        attr[0].id = cudaLaunchAttributeProgrammaticStreamSerialization;
        attr[0].val.programmaticStreamSerializationAllowed = 1;
        cfg.attrs = attr;
        cfg.numAttrs = 1;
        cudaLaunchKernelEx(&cfg, gemm_fused, bfc);
    }

    // K3: PDL launch (overlaps with gemm's drain)
    {
        cudaLaunchConfig_t cfg = {};
        cfg.gridDim = dim3(TAIL_BLOCKS, 1, 1);
        cfg.blockDim = dim3(256, 1, 1);
        cfg.dynamicSmemBytes = 0;
        cfg.stream = 0;
        cudaLaunchAttribute attr[1];
        attr[0].id = cudaLaunchAttributeProgrammaticStreamSerialization;
        attr[0].val.programmaticStreamSerializationAllowed = 1;
        cfg.attrs = attr;
        cfg.numAttrs = 1;
        cudaLaunchKernelEx(&cfg, tail_kernel, gamma, beta, out);
    }
}